// round 13
// baseline (speedup 1.0000x reference)
#include <cuda_runtime.h>

#define B_TOT   8192
#define T_IN    1024
#define T_OUT   1088               // 1024 + 64 free-running
#define EPB     32                 // elements per block
#define THREADS 96                 // u = tid>>3 (unit 0..11), s = tid&7; elems s+8i, i=0..3
#define CHUNK   32
#define NCHUNK  (T_OUT / CHUNK)    // 34
#define XSTF    33                 // xbuf/ybuf float row stride (odd)
#define HST     14                 // h buffers ull row stride (7 float4 -> conflict-free)

typedef unsigned long long ull;

__device__ __forceinline__ ull pk2(float lo, float hi) {
    ull r; asm("mov.b64 %0, {%1, %2};" : "=l"(r) : "f"(lo), "f"(hi)); return r;
}
__device__ __forceinline__ ull ffma2(ull a, ull b, ull c) {
    ull d; asm("fma.rn.f32x2 %0, %1, %2, %3;" : "=l"(d) : "l"(a), "l"(b), "l"(c)); return d;
}
__device__ __forceinline__ float2 unpk(ull v) {
    float lo, hi; asm("mov.b64 {%0, %1}, %2;" : "=f"(lo), "=f"(hi) : "l"(v));
    return make_float2(lo, hi);
}
__device__ __forceinline__ float tanh_fast(float x) {
    float y; asm("tanh.approx.f32 %0, %1;" : "=f"(y) : "f"(x)); return y;
}
__device__ __forceinline__ float sigf(float x) {
    return fmaf(tanh_fast(0.5f * x), 0.5f, 0.5f);
}

__global__ __launch_bounds__(THREADS)
void lstm_seq_kernel(const float* __restrict__ input,
                     const float* __restrict__ w_ih1, const float* __restrict__ w_hh1,
                     const float* __restrict__ b_ih1, const float* __restrict__ b_hh1,
                     const float* __restrict__ w_ih2, const float* __restrict__ w_hh2,
                     const float* __restrict__ b_ih2, const float* __restrict__ b_hh2,
                     const float* __restrict__ w_lin, const float* __restrict__ b_lin,
                     float* __restrict__ out)
{
    // gate-packed unit-contiguous weights (R12 layout): ull idx = ((q*6+jj)*12+u)*2+t,
    // j = 2jj+t; q=0 -> rows (u,12+u)=(i,f); q=1 -> (24+u,36+u)=(g,o)
    __shared__ alignas(16) ull s_w1[288], s_wi2[288], s_wh2[288];
    __shared__ alignas(16) ull s_wl[12];
    __shared__ alignas(16) float xbuf[CHUNK * XSTF];
    __shared__ alignas(16) float ybuf[CHUNK * XSTF];
    __shared__ alignas(16) ull h1buf[2][EPB * HST];   // (h,h) packed, parity-buffered
    __shared__ alignas(16) ull h2buf[2][EPB * HST];

    const int tid = threadIdx.x;
    const int u   = tid >> 3;      // owned unit
    const int s   = tid & 7;       // element slot; elements s, s+8, s+16, s+24

    for (int idx = tid; idx < 288; idx += THREADS) {
        const int t  = idx & 1;
        const int r2 = idx >> 1;
        const int uu = r2 % 12;
        const int pos = r2 / 12;
        const int jj = pos % 6;
        const int q  = pos / 6;
        const int j  = 2 * jj + t;
        const int rA = (q ? 24 : 0) + uu;
        const int rB = (q ? 36 : 12) + uu;
        s_w1[idx]  = pk2(w_hh1[rA * 12 + j], w_hh1[rB * 12 + j]);
        s_wi2[idx] = pk2(w_ih2[rA * 12 + j], w_ih2[rB * 12 + j]);
        s_wh2[idx] = pk2(w_hh2[rA * 12 + j], w_hh2[rB * 12 + j]);
    }
    if (tid < 12) s_wl[tid] = pk2(w_lin[tid], w_lin[tid]);
    for (int idx = tid; idx < 2 * EPB * HST; idx += THREADS) {
        ((ull*)h1buf)[idx] = 0ULL;
        ((ull*)h2buf)[idx] = 0ULL;
    }

    const ull wx_if  = pk2(w_ih1[u],      w_ih1[12 + u]);
    const ull wx_go  = pk2(w_ih1[24 + u], w_ih1[36 + u]);
    const ull bz1_if = pk2(b_ih1[u] + b_hh1[u],           b_ih1[12 + u] + b_hh1[12 + u]);
    const ull bz1_go = pk2(b_ih1[24 + u] + b_hh1[24 + u], b_ih1[36 + u] + b_hh1[36 + u]);
    const ull bz2_if = pk2(b_ih2[u] + b_hh2[u],           b_ih2[12 + u] + b_hh2[12 + u]);
    const ull bz2_go = pk2(b_ih2[24 + u] + b_hh2[24 + u], b_ih2[36 + u] + b_hh2[36 + u]);
    const float blin = b_lin[0];

    float c1[4] = {0.f, 0.f, 0.f, 0.f};
    float c2[4] = {0.f, 0.f, 0.f, 0.f};

    const size_t eg0 = (size_t)blockIdx.x * EPB;
    const ulonglong2* w1v  = (const ulonglong2*)s_w1;
    const ulonglong2* wi2v = (const ulonglong2*)s_wi2;
    const ulonglong2* wh2v = (const ulonglong2*)s_wh2;

    __syncthreads();

    for (int ck = 0; ck < NCHUNK; ck++) {
        const int tbase = ck * CHUNK;

        // ---- stage x chunk (tid<64: 2 threads per element, 16 steps each) ----
        if (tid < 64) {
            const int ee = tid & 31, half = tid >> 5;
            const float* src = input + (eg0 + ee) * T_IN;
            if (tbase < T_IN) {
                const float4* p = (const float4*)(src + tbase + half * 16);
                #pragma unroll
                for (int q = 0; q < 4; q++) {
                    float4 v = p[q];
                    const int t0 = half * 16 + q * 4;
                    xbuf[(t0 + 0) * XSTF + ee] = v.x;
                    xbuf[(t0 + 1) * XSTF + ee] = v.y;
                    xbuf[(t0 + 2) * XSTF + ee] = v.z;
                    xbuf[(t0 + 3) * XSTF + ee] = v.w;
                }
            } else {
                const float xl = src[T_IN - 1];   // free-running: repeat last input
                #pragma unroll
                for (int kk = 0; kk < 16; kk++)
                    xbuf[(half * 16 + kk) * XSTF + ee] = xl;
            }
        }
        __syncthreads();

        #pragma unroll 1
        for (int is = 0; is < CHUNK; is++) {
            const int k    = tbase + is;
            const int wsel = k & 1, rsel = wsel ^ 1;

            // ---- gather h1(k-1) for all 4 elements into registers ----
            ull hh1[4][12];
            #pragma unroll
            for (int i = 0; i < 4; i++) {
                #pragma unroll
                for (int jj = 0; jj < 6; jj++) {
                    ulonglong2 v = *(const ulonglong2*)&h1buf[rsel][(s + 8 * i) * HST + 2 * jj];
                    hh1[i][2 * jj] = v.x; hh1[i][2 * jj + 1] = v.y;
                }
            }

            // ---- layer 1: h1(k) = f(x(k), h1(k-1)) ----
            {
                ull aif[4], ago[4];
                #pragma unroll
                for (int i = 0; i < 4; i++) {
                    const float x = xbuf[is * XSTF + s + 8 * i];
                    const ull xx = pk2(x, x);
                    aif[i] = ffma2(xx, wx_if, bz1_if);
                    ago[i] = ffma2(xx, wx_go, bz1_go);
                }
                #pragma unroll
                for (int jj = 0; jj < 6; jj++) {
                    ulonglong2 wif = w1v[jj * 12 + u];
                    ulonglong2 wgo = w1v[(6 + jj) * 12 + u];
                    #pragma unroll
                    for (int i = 0; i < 4; i++) {
                        aif[i] = ffma2(hh1[i][2 * jj],     wif.x, aif[i]);
                        aif[i] = ffma2(hh1[i][2 * jj + 1], wif.y, aif[i]);
                        ago[i] = ffma2(hh1[i][2 * jj],     wgo.x, ago[i]);
                        ago[i] = ffma2(hh1[i][2 * jj + 1], wgo.y, ago[i]);
                    }
                }
                #pragma unroll
                for (int i = 0; i < 4; i++) {
                    float2 gif = unpk(aif[i]), ggo = unpk(ago[i]);
                    float cc = fmaf(sigf(gif.y), c1[i], sigf(gif.x) * tanh_fast(ggo.x));
                    c1[i] = cc;
                    float hn = sigf(ggo.y) * tanh_fast(cc);
                    h1buf[wsel][(s + 8 * i) * HST + u] = pk2(hn, hn);
                }
            }

            // ---- layer 2: h2(k-1) = g(h1(k-1), h2(k-2)); h2 slices streamed ----
            if (k >= 1) {
                ull bif[4], bgo[4];
                #pragma unroll
                for (int i = 0; i < 4; i++) { bif[i] = bz2_if; bgo[i] = bz2_go; }
                #pragma unroll
                for (int jj = 0; jj < 6; jj++) {
                    ulonglong2 wiif = wi2v[jj * 12 + u];
                    ulonglong2 wigo = wi2v[(6 + jj) * 12 + u];
                    ulonglong2 whif = wh2v[jj * 12 + u];
                    ulonglong2 whgo = wh2v[(6 + jj) * 12 + u];
                    #pragma unroll
                    for (int i = 0; i < 4; i++) {
                        ulonglong2 hv = *(const ulonglong2*)&h2buf[rsel][(s + 8 * i) * HST + 2 * jj];
                        bif[i] = ffma2(hh1[i][2 * jj],     wiif.x, bif[i]);
                        bif[i] = ffma2(hh1[i][2 * jj + 1], wiif.y, bif[i]);
                        bgo[i] = ffma2(hh1[i][2 * jj],     wigo.x, bgo[i]);
                        bgo[i] = ffma2(hh1[i][2 * jj + 1], wigo.y, bgo[i]);
                        bif[i] = ffma2(hv.x, whif.x, bif[i]);
                        bif[i] = ffma2(hv.y, whif.y, bif[i]);
                        bgo[i] = ffma2(hv.x, whgo.x, bgo[i]);
                        bgo[i] = ffma2(hv.y, whgo.y, bgo[i]);
                    }
                }
                #pragma unroll
                for (int i = 0; i < 4; i++) {
                    float2 gif = unpk(bif[i]), ggo = unpk(bgo[i]);
                    float cc = fmaf(sigf(gif.y), c2[i], sigf(gif.x) * tanh_fast(ggo.x));
                    c2[i] = cc;
                    float hn = sigf(ggo.y) * tanh_fast(cc);
                    h2buf[wsel][(s + 8 * i) * HST + u] = pk2(hn, hn);
                }
            }

            // ---- head: y(k-2) from h2buf[rsel] (unit-0 threads only) ----
            if (u == 0 && k >= 2) {
                #pragma unroll
                for (int i = 0; i < 4; i++) {
                    ull y = pk2(blin, blin);
                    #pragma unroll
                    for (int jj = 0; jj < 6; jj++) {
                        ulonglong2 hv = *(const ulonglong2*)&h2buf[rsel][(s + 8 * i) * HST + 2 * jj];
                        y = ffma2(hv.x, s_wl[2 * jj],     y);
                        y = ffma2(hv.y, s_wl[2 * jj + 1], y);
                    }
                    ybuf[is * XSTF + s + 8 * i] = unpk(y).x;
                }
            }
            __syncthreads();   // the ONLY per-step barrier
        }

        // ---- drain ybuf: slot j holds y(tbase-2+j) ----
        if (tid < 64) {
            const int ee = tid & 31, half = tid >> 5;
            #pragma unroll
            for (int q = 0; q < 8; q++) {
                const int j = half * 16 + q * 2;
                const int t = tbase - 2 + j;
                if (t >= 0) {
                    float2 v = make_float2(ybuf[j * XSTF + ee], ybuf[(j + 1) * XSTF + ee]);
                    *(float2*)(out + (eg0 + ee) * T_OUT + t) = v;
                }
            }
        }
    }

    // ---- epilogue: y(1086); h2(1087); y(1087) ----
    // After the loop: h1buf[1] = h1(1087), h2buf[1] = h2(1086), c2 = c(1086).
    if (u == 0) {
        #pragma unroll
        for (int i = 0; i < 4; i++) {
            ull y = pk2(blin, blin);
            #pragma unroll
            for (int jj = 0; jj < 6; jj++) {
                ulonglong2 hv = *(const ulonglong2*)&h2buf[1][(s + 8 * i) * HST + 2 * jj];
                y = ffma2(hv.x, s_wl[2 * jj],     y);
                y = ffma2(hv.y, s_wl[2 * jj + 1], y);
            }
            out[(eg0 + s + 8 * i) * T_OUT + (T_OUT - 2)] = unpk(y).x;
        }
    }
    {
        // h2(1087) = g(h1(1087), h2(1086)), element by element (reg-light)
        #pragma unroll 1
        for (int i = 0; i < 4; i++) {
            const int e = s + 8 * i;
            ull bif = bz2_if, bgo = bz2_go;
            #pragma unroll
            for (int jj = 0; jj < 6; jj++) {
                ulonglong2 h1v = *(const ulonglong2*)&h1buf[1][e * HST + 2 * jj];
                ulonglong2 h2v = *(const ulonglong2*)&h2buf[1][e * HST + 2 * jj];
                ulonglong2 wiif = wi2v[jj * 12 + u];
                ulonglong2 wigo = wi2v[(6 + jj) * 12 + u];
                ulonglong2 whif = wh2v[jj * 12 + u];
                ulonglong2 whgo = wh2v[(6 + jj) * 12 + u];
                bif = ffma2(h1v.x, wiif.x, bif);
                bif = ffma2(h1v.y, wiif.y, bif);
                bgo = ffma2(h1v.x, wigo.x, bgo);
                bgo = ffma2(h1v.y, wigo.y, bgo);
                bif = ffma2(h2v.x, whif.x, bif);
                bif = ffma2(h2v.y, whif.y, bif);
                bgo = ffma2(h2v.x, whgo.x, bgo);
                bgo = ffma2(h2v.y, whgo.y, bgo);
            }
            float2 gif = unpk(bif), ggo = unpk(bgo);
            float cc = fmaf(sigf(gif.y), c2[i], sigf(gif.x) * tanh_fast(ggo.x));
            float hn = sigf(ggo.y) * tanh_fast(cc);
            h2buf[0][e * HST + u] = pk2(hn, hn);
        }
    }
    __syncthreads();
    if (u == 0) {
        #pragma unroll
        for (int i = 0; i < 4; i++) {
            ull y = pk2(blin, blin);
            #pragma unroll
            for (int jj = 0; jj < 6; jj++) {
                ulonglong2 hv = *(const ulonglong2*)&h2buf[0][(s + 8 * i) * HST + 2 * jj];
                y = ffma2(hv.x, s_wl[2 * jj],     y);
                y = ffma2(hv.y, s_wl[2 * jj + 1], y);
            }
            out[(eg0 + s + 8 * i) * T_OUT + (T_OUT - 1)] = unpk(y).x;
        }
    }
}

extern "C" void kernel_launch(void* const* d_in, const int* in_sizes, int n_in,
                              void* d_out, int out_size) {
    // metadata order: input, future(int scalar), w_ih1, w_hh1, b_ih1, b_hh1,
    //                 w_ih2, w_hh2, b_ih2, b_hh2, w_lin, b_lin
    int base = (n_in >= 12 && in_sizes[1] == 1) ? 2 : 1;  // skip 'future' scalar if present
    const float* input = (const float*)d_in[0];
    const float* w_ih1 = (const float*)d_in[base + 0];
    const float* w_hh1 = (const float*)d_in[base + 1];
    const float* b_ih1 = (const float*)d_in[base + 2];
    const float* b_hh1 = (const float*)d_in[base + 3];
    const float* w_ih2 = (const float*)d_in[base + 4];
    const float* w_hh2 = (const float*)d_in[base + 5];
    const float* b_ih2 = (const float*)d_in[base + 6];
    const float* b_hh2 = (const float*)d_in[base + 7];
    const float* w_lin = (const float*)d_in[base + 8];
    const float* b_lin = (const float*)d_in[base + 9];

    lstm_seq_kernel<<<B_TOT / EPB, THREADS>>>(
        input, w_ih1, w_hh1, b_ih1, b_hh1,
        w_ih2, w_hh2, b_ih2, b_hh2, w_lin, b_lin,
        (float*)d_out);
}

// round 14
// speedup vs baseline: 1.1361x; 1.1361x over previous
#include <cuda_runtime.h>

#define B_TOT   8192
#define T_IN    1024
#define T_OUT   1088               // 1024 + 64 free-running
#define EPB     32                 // elements per block; lane = element
#define THREADS 128                // 4 warps; warp w owns units 3w..3w+2
#define CHUNK   32
#define NCHUNK  (T_OUT / CHUNK)    // 34
#define XSTF    33                 // xbuf/ybuf float row stride (odd)
#define HROW    12                 // h row stride floats (48B, float4-aligned, min-wavefront)

typedef unsigned long long ull;

__device__ __forceinline__ ull pk2(float lo, float hi) {
    ull r; asm("mov.b64 %0, {%1, %2};" : "=l"(r) : "f"(lo), "f"(hi)); return r;
}
__device__ __forceinline__ ull ffma2(ull a, ull b, ull c) {
    ull d; asm("fma.rn.f32x2 %0, %1, %2, %3;" : "=l"(d) : "l"(a), "l"(b), "l"(c)); return d;
}
__device__ __forceinline__ float2 unpk(ull v) {
    float lo, hi; asm("mov.b64 {%0, %1}, %2;" : "=f"(lo), "=f"(hi) : "l"(v));
    return make_float2(lo, hi);
}
__device__ __forceinline__ float tanh_fast(float x) {
    float y; asm("tanh.approx.f32 %0, %1;" : "=f"(y) : "f"(x)); return y;
}
// prescaled sigmoid: weights/biases already carry the 0.5 factor
__device__ __forceinline__ float sigp(float a) {
    return fmaf(tanh_fast(a), 0.5f, 0.5f);
}

// pair-row dot: warp-uniform base -> 6 broadcast LDS.128, 12 FFMA2
__device__ __forceinline__ void dot12(const ulonglong2* __restrict__ p,
                                      const ull* hh, ull& a) {
    #pragma unroll
    for (int jj = 0; jj < 6; jj++) {
        ulonglong2 v = p[jj];
        a = ffma2(hh[2 * jj],     v.x, a);
        a = ffma2(hh[2 * jj + 1], v.y, a);
    }
}

__global__ __launch_bounds__(THREADS)
void lstm_seq_kernel(const float* __restrict__ input,
                     const float* __restrict__ w_ih1, const float* __restrict__ w_hh1,
                     const float* __restrict__ b_ih1, const float* __restrict__ b_hh1,
                     const float* __restrict__ w_ih2, const float* __restrict__ w_hh2,
                     const float* __restrict__ b_ih2, const float* __restrict__ b_hh2,
                     const float* __restrict__ w_lin, const float* __restrict__ b_lin,
                     float* __restrict__ out)
{
    // gate-packed weights [ (u*2+pair)*12 + j ] = pk2(sA*W[rA*12+j], 0.5*W[rB*12+j])
    // pair0: rA=u (i), rB=12+u (f), sA=0.5;  pair1: rA=24+u (g, sA=1.0), rB=36+u (o)
    __shared__ alignas(16) ull s_w1[288], s_wi2[288], s_wh2[288];
    __shared__ alignas(16) float s_wl[12];
    __shared__ float s_blin;
    __shared__ alignas(16) float xbuf[CHUNK * XSTF];
    __shared__ alignas(16) float ybuf[CHUNK * XSTF];
    __shared__ alignas(16) float h1buf[2][EPB * HROW];   // PLAIN floats, parity-buffered
    __shared__ alignas(16) float h2buf[2][EPB * HROW];

    const int tid = threadIdx.x;
    const int wid = tid >> 5;      // warp owns units 3*wid .. 3*wid+2
    const int e   = tid & 31;      // owned element

    for (int idx = tid; idx < 288; idx += THREADS) {
        const int u = idx / 24, rem = idx % 24, p = rem / 12, j = rem % 12;
        const int rA = (p ? 24 : 0) + u;
        const int rB = (p ? 36 : 12) + u;
        const float sA = p ? 1.0f : 0.5f;
        s_w1[idx]  = pk2(sA * w_hh1[rA * 12 + j], 0.5f * w_hh1[rB * 12 + j]);
        s_wi2[idx] = pk2(sA * w_ih2[rA * 12 + j], 0.5f * w_ih2[rB * 12 + j]);
        s_wh2[idx] = pk2(sA * w_hh2[rA * 12 + j], 0.5f * w_hh2[rB * 12 + j]);
    }
    if (tid < 12) s_wl[tid] = w_lin[tid];
    if (tid == 0) s_blin = b_lin[0];
    for (int idx = tid; idx < 2 * EPB * HROW; idx += THREADS) {
        ((float*)h1buf)[idx] = 0.0f;
        ((float*)h2buf)[idx] = 0.0f;
    }

    // per-thread packed constants for 3 owned units (prescaled)
    ull wx_if[3], wx_go[3], bz1_if[3], bz1_go[3], bz2_if[3], bz2_go[3];
    #pragma unroll
    for (int m = 0; m < 3; m++) {
        const int u = 3 * wid + m;
        wx_if[m]  = pk2(0.5f * w_ih1[u],       0.5f * w_ih1[12 + u]);
        wx_go[m]  = pk2(w_ih1[24 + u],         0.5f * w_ih1[36 + u]);
        bz1_if[m] = pk2(0.5f * (b_ih1[u] + b_hh1[u]),
                        0.5f * (b_ih1[12 + u] + b_hh1[12 + u]));
        bz1_go[m] = pk2((b_ih1[24 + u] + b_hh1[24 + u]),
                        0.5f * (b_ih1[36 + u] + b_hh1[36 + u]));
        bz2_if[m] = pk2(0.5f * (b_ih2[u] + b_hh2[u]),
                        0.5f * (b_ih2[12 + u] + b_hh2[12 + u]));
        bz2_go[m] = pk2((b_ih2[24 + u] + b_hh2[24 + u]),
                        0.5f * (b_ih2[36 + u] + b_hh2[36 + u]));
    }
    float c1[3] = {0.f, 0.f, 0.f};
    float c2[3] = {0.f, 0.f, 0.f};

    const size_t eg0 = (size_t)blockIdx.x * EPB;
    __syncthreads();

    for (int ck = 0; ck < NCHUNK; ck++) {
        const int tbase = ck * CHUNK;

        // ---- stage x chunk (tid<64: 2 threads per element, 16 steps each) ----
        if (tid < 64) {
            const int ee = tid & 31, half = tid >> 5;
            const float* src = input + (eg0 + ee) * T_IN;
            if (tbase < T_IN) {
                const float4* p = (const float4*)(src + tbase + half * 16);
                #pragma unroll
                for (int q = 0; q < 4; q++) {
                    float4 v = p[q];
                    const int t0 = half * 16 + q * 4;
                    xbuf[(t0 + 0) * XSTF + ee] = v.x;
                    xbuf[(t0 + 1) * XSTF + ee] = v.y;
                    xbuf[(t0 + 2) * XSTF + ee] = v.z;
                    xbuf[(t0 + 3) * XSTF + ee] = v.w;
                }
            } else {
                const float xl = src[T_IN - 1];   // free-running: repeat last input
                #pragma unroll
                for (int kk = 0; kk < 16; kk++)
                    xbuf[(half * 16 + kk) * XSTF + ee] = xl;
            }
        }
        __syncthreads();

        #pragma unroll 1
        for (int is = 0; is < CHUNK; is++) {
            const int k    = tbase + is;
            const int wsel = k & 1, rsel = wsel ^ 1;

            // ---- gather h1(k-1), h2(k-2): 3+3 LDS.128, replicate via ALU movs ----
            ull hh1[12], hh2[12];
            float h2f0, h2f1, h2f2, h2f3;   // keep a few floats for the head
            {
                const float4* r1 = (const float4*)&h1buf[rsel][e * HROW];
                float4 A = r1[0], B = r1[1], C = r1[2];
                hh1[0] = pk2(A.x, A.x); hh1[1] = pk2(A.y, A.y);
                hh1[2] = pk2(A.z, A.z); hh1[3] = pk2(A.w, A.w);
                hh1[4] = pk2(B.x, B.x); hh1[5] = pk2(B.y, B.y);
                hh1[6] = pk2(B.z, B.z); hh1[7] = pk2(B.w, B.w);
                hh1[8] = pk2(C.x, C.x); hh1[9] = pk2(C.y, C.y);
                hh1[10] = pk2(C.z, C.z); hh1[11] = pk2(C.w, C.w);
            }
            {
                const float4* r2 = (const float4*)&h2buf[rsel][e * HROW];
                float4 D = r2[0], E = r2[1], F = r2[2];
                hh2[0] = pk2(D.x, D.x); hh2[1] = pk2(D.y, D.y);
                hh2[2] = pk2(D.z, D.z); hh2[3] = pk2(D.w, D.w);
                hh2[4] = pk2(E.x, E.x); hh2[5] = pk2(E.y, E.y);
                hh2[6] = pk2(E.z, E.z); hh2[7] = pk2(E.w, E.w);
                hh2[8] = pk2(F.x, F.x); hh2[9] = pk2(F.y, F.y);
                hh2[10] = pk2(F.z, F.z); hh2[11] = pk2(F.w, F.w);
                // head (warp 0 only) computed below from hh2 via unpk-free floats:
                h2f0 = D.x; h2f1 = D.y; h2f2 = D.z; h2f3 = D.w;
                if (wid == 0 && k >= 2) {
                    float y = s_blin;
                    y = fmaf(D.x, s_wl[0], y);  y = fmaf(D.y, s_wl[1], y);
                    y = fmaf(D.z, s_wl[2], y);  y = fmaf(D.w, s_wl[3], y);
                    y = fmaf(E.x, s_wl[4], y);  y = fmaf(E.y, s_wl[5], y);
                    y = fmaf(E.z, s_wl[6], y);  y = fmaf(E.w, s_wl[7], y);
                    y = fmaf(F.x, s_wl[8], y);  y = fmaf(F.y, s_wl[9], y);
                    y = fmaf(F.z, s_wl[10], y); y = fmaf(F.w, s_wl[11], y);
                    ybuf[is * XSTF + e] = y;
                }
            }
            (void)h2f0; (void)h2f1; (void)h2f2; (void)h2f3;

            const float x = xbuf[is * XSTF + e];
            const ull xx = pk2(x, x);

            // ---- layer 1: h1(k) = f(x(k), h1(k-1)) ----
            #pragma unroll
            for (int m = 0; m < 3; m++) {
                const int u = 3 * wid + m;
                ull aif = ffma2(xx, wx_if[m], bz1_if[m]);
                ull ago = ffma2(xx, wx_go[m], bz1_go[m]);
                dot12((const ulonglong2*)&s_w1[(u * 2 + 0) * 12], hh1, aif);
                dot12((const ulonglong2*)&s_w1[(u * 2 + 1) * 12], hh1, ago);
                float2 gif = unpk(aif), ggo = unpk(ago);
                float cc = fmaf(sigp(gif.y), c1[m], sigp(gif.x) * tanh_fast(ggo.x));
                c1[m] = cc;
                h1buf[wsel][e * HROW + u] = sigp(ggo.y) * tanh_fast(cc);
            }

            // ---- layer 2: h2(k-1) = g(h1(k-1), h2(k-2)) ----
            if (k >= 1) {
                #pragma unroll
                for (int m = 0; m < 3; m++) {
                    const int u = 3 * wid + m;
                    ull aif = bz2_if[m];
                    ull ago = bz2_go[m];
                    dot12((const ulonglong2*)&s_wi2[(u * 2 + 0) * 12], hh1, aif);
                    dot12((const ulonglong2*)&s_wi2[(u * 2 + 1) * 12], hh1, ago);
                    dot12((const ulonglong2*)&s_wh2[(u * 2 + 0) * 12], hh2, aif);
                    dot12((const ulonglong2*)&s_wh2[(u * 2 + 1) * 12], hh2, ago);
                    float2 gif = unpk(aif), ggo = unpk(ago);
                    float cc = fmaf(sigp(gif.y), c2[m], sigp(gif.x) * tanh_fast(ggo.x));
                    c2[m] = cc;
                    h2buf[wsel][e * HROW + u] = sigp(ggo.y) * tanh_fast(cc);
                }
            }
            __syncthreads();   // the ONLY per-step barrier
        }

        // ---- drain ybuf: slot j holds y(tbase-2+j) ----
        if (tid < 64) {
            const int ee = tid & 31, half = tid >> 5;
            #pragma unroll
            for (int q = 0; q < 8; q++) {
                const int j = half * 16 + q * 2;
                const int t = tbase - 2 + j;
                if (t >= 0) {
                    float2 v = make_float2(ybuf[j * XSTF + ee], ybuf[(j + 1) * XSTF + ee]);
                    *(float2*)(out + (eg0 + ee) * T_OUT + t) = v;
                }
            }
        }
    }

    // ---- epilogue: after loop h1buf[1]=h1(1087), h2buf[1]=h2(1086), c2=c2(1086) ----
    {
        ull hh1[12], hh2[12];
        {
            const float4* r1 = (const float4*)&h1buf[1][e * HROW];
            float4 A = r1[0], B = r1[1], C = r1[2];
            hh1[0] = pk2(A.x, A.x); hh1[1] = pk2(A.y, A.y);
            hh1[2] = pk2(A.z, A.z); hh1[3] = pk2(A.w, A.w);
            hh1[4] = pk2(B.x, B.x); hh1[5] = pk2(B.y, B.y);
            hh1[6] = pk2(B.z, B.z); hh1[7] = pk2(B.w, B.w);
            hh1[8] = pk2(C.x, C.x); hh1[9] = pk2(C.y, C.y);
            hh1[10] = pk2(C.z, C.z); hh1[11] = pk2(C.w, C.w);
        }
        {
            const float4* r2 = (const float4*)&h2buf[1][e * HROW];
            float4 D = r2[0], E = r2[1], F = r2[2];
            hh2[0] = pk2(D.x, D.x); hh2[1] = pk2(D.y, D.y);
            hh2[2] = pk2(D.z, D.z); hh2[3] = pk2(D.w, D.w);
            hh2[4] = pk2(E.x, E.x); hh2[5] = pk2(E.y, E.y);
            hh2[6] = pk2(E.z, E.z); hh2[7] = pk2(E.w, E.w);
            hh2[8] = pk2(F.x, F.x); hh2[9] = pk2(F.y, F.y);
            hh2[10] = pk2(F.z, F.z); hh2[11] = pk2(F.w, F.w);
            if (wid == 0) {   // y(1086)
                float y = s_blin;
                y = fmaf(D.x, s_wl[0], y);  y = fmaf(D.y, s_wl[1], y);
                y = fmaf(D.z, s_wl[2], y);  y = fmaf(D.w, s_wl[3], y);
                y = fmaf(E.x, s_wl[4], y);  y = fmaf(E.y, s_wl[5], y);
                y = fmaf(E.z, s_wl[6], y);  y = fmaf(E.w, s_wl[7], y);
                y = fmaf(F.x, s_wl[8], y);  y = fmaf(F.y, s_wl[9], y);
                y = fmaf(F.z, s_wl[10], y); y = fmaf(F.w, s_wl[11], y);
                out[(eg0 + e) * T_OUT + (T_OUT - 2)] = y;
            }
        }
        // h2(1087) = g(h1(1087), h2(1086))
        #pragma unroll
        for (int m = 0; m < 3; m++) {
            const int u = 3 * wid + m;
            ull aif = bz2_if[m];
            ull ago = bz2_go[m];
            dot12((const ulonglong2*)&s_wi2[(u * 2 + 0) * 12], hh1, aif);
            dot12((const ulonglong2*)&s_wi2[(u * 2 + 1) * 12], hh1, ago);
            dot12((const ulonglong2*)&s_wh2[(u * 2 + 0) * 12], hh2, aif);
            dot12((const ulonglong2*)&s_wh2[(u * 2 + 1) * 12], hh2, ago);
            float2 gif = unpk(aif), ggo = unpk(ago);
            float cc = fmaf(sigp(gif.y), c2[m], sigp(gif.x) * tanh_fast(ggo.x));
            h2buf[0][e * HROW + u] = sigp(ggo.y) * tanh_fast(cc);
        }
        __syncthreads();
        if (wid == 0) {   // y(1087)
            const float4* r = (const float4*)&h2buf[0][e * HROW];
            float4 D = r[0], E = r[1], F = r[2];
            float y = s_blin;
            y = fmaf(D.x, s_wl[0], y);  y = fmaf(D.y, s_wl[1], y);
            y = fmaf(D.z, s_wl[2], y);  y = fmaf(D.w, s_wl[3], y);
            y = fmaf(E.x, s_wl[4], y);  y = fmaf(E.y, s_wl[5], y);
            y = fmaf(E.z, s_wl[6], y);  y = fmaf(E.w, s_wl[7], y);
            y = fmaf(F.x, s_wl[8], y);  y = fmaf(F.y, s_wl[9], y);
            y = fmaf(F.z, s_wl[10], y); y = fmaf(F.w, s_wl[11], y);
            out[(eg0 + e) * T_OUT + (T_OUT - 1)] = y;
        }
    }
}

extern "C" void kernel_launch(void* const* d_in, const int* in_sizes, int n_in,
                              void* d_out, int out_size) {
    // metadata order: input, future(int scalar), w_ih1, w_hh1, b_ih1, b_hh1,
    //                 w_ih2, w_hh2, b_ih2, b_hh2, w_lin, b_lin
    int base = (n_in >= 12 && in_sizes[1] == 1) ? 2 : 1;  // skip 'future' scalar if present
    const float* input = (const float*)d_in[0];
    const float* w_ih1 = (const float*)d_in[base + 0];
    const float* w_hh1 = (const float*)d_in[base + 1];
    const float* b_ih1 = (const float*)d_in[base + 2];
    const float* b_hh1 = (const float*)d_in[base + 3];
    const float* w_ih2 = (const float*)d_in[base + 4];
    const float* w_hh2 = (const float*)d_in[base + 5];
    const float* b_ih2 = (const float*)d_in[base + 6];
    const float* b_hh2 = (const float*)d_in[base + 7];
    const float* w_lin = (const float*)d_in[base + 8];
    const float* b_lin = (const float*)d_in[base + 9];

    lstm_seq_kernel<<<B_TOT / EPB, THREADS>>>(
        input, w_ih1, w_hh1, b_ih1, b_hh1,
        w_ih2, w_hh2, b_ih2, b_hh2, w_lin, b_lin,
        (float*)d_out);
}